// round 5
// baseline (speedup 1.0000x reference)
#include <cuda_runtime.h>
#include <cuda_bf16.h>
#include <math.h>

// Problem constants
#define BT      2
#define ST      2048
#define T_TOK   4096          // B*S
#define H_DIM   1024
#define I_DIM   2048
#define E_NUM   8
#define TOPK    2
#define NSLOT   (T_TOK * TOPK)   // 8192 assignment rows total (always exactly this)

#define BM 64
#define BN 128
#define BK 16
#define MAX_ROW_TILES 136   // ceil(8192/64) + (E-1) worst case

// ---------------- scratch (device globals: no allocation allowed) ----------------
__device__ int   g_cnt[E_NUM];
__device__ int   g_off[E_NUM + 1];
__device__ int   g_tok_exp[NSLOT];
__device__ float g_tok_wt[NSLOT];
__device__ int   g_tok_rank[NSLOT];
__device__ int   g_perm[NSLOT];       // slot -> token
__device__ float g_pwt[NSLOT];        // slot -> routing weight
__device__ float g_hidden[(size_t)NSLOT * I_DIM];   // 64 MB intermediate

// ---------------- packed f32x2 helpers ----------------
#define PACK2(d, s) \
    asm("mov.b64 %0, {%1, %1};" : "=l"(d) : "f"(s))
#define UNPACK2(lo, hi, v) \
    asm("mov.b64 {%0, %1}, %2;" : "=f"(lo), "=f"(hi) : "l"(v))
#define FMA2(acc, a, b) \
    asm("fma.rn.f32x2 %0, %1, %2, %0;" : "+l"(acc) : "l"(a), "l"(b))

// ---------------- small kernels ----------------
__global__ void zero_cnt_kernel() {
    if (threadIdx.x < E_NUM) g_cnt[threadIdx.x] = 0;
}

__global__ void scan_off_kernel() {
    if (threadIdx.x == 0) {
        int a = 0;
        for (int e = 0; e < E_NUM; e++) { g_off[e] = a; a += g_cnt[e]; }
        g_off[E_NUM] = a;
    }
}

__global__ void build_perm_kernel() {
    int idx = blockIdx.x * blockDim.x + threadIdx.x;
    if (idx < NSLOT) {
        int e = g_tok_exp[idx];
        int slot = g_off[e] + g_tok_rank[idx];
        g_perm[slot] = idx >> 1;
        g_pwt[slot]  = g_tok_wt[idx];
    }
}

// Router: one block per token, one warp per expert (E=8 warps = 256 threads)
__global__ void router_kernel(const float* __restrict__ x,
                              const float* __restrict__ rw,
                              float* __restrict__ logits_out,
                              int write_logits) {
    int t = blockIdx.x;
    int warp = threadIdx.x >> 5, lane = threadIdx.x & 31;
    const float* xr = x + (size_t)t * H_DIM;
    float s = 0.f;
    for (int h = lane; h < H_DIM; h += 32)
        s += xr[h] * rw[h * E_NUM + warp];
#pragma unroll
    for (int o = 16; o; o >>= 1) s += __shfl_xor_sync(0xffffffffu, s, o);

    __shared__ float lg[E_NUM];
    if (lane == 0) lg[warp] = s;
    __syncthreads();

    if (threadIdx.x == 0) {
        float l[E_NUM], mx = -1e30f;
#pragma unroll
        for (int e = 0; e < E_NUM; e++) { l[e] = lg[e]; mx = fmaxf(mx, l[e]); }
        float p[E_NUM], sum = 0.f;
#pragma unroll
        for (int e = 0; e < E_NUM; e++) { p[e] = expf(l[e] - mx); sum += p[e]; }
#pragma unroll
        for (int e = 0; e < E_NUM; e++) p[e] /= sum;

        int i1 = 0;
#pragma unroll
        for (int e = 1; e < E_NUM; e++) if (p[e] > p[i1]) i1 = e;
        int i2 = (i1 == 0) ? 1 : 0;
#pragma unroll
        for (int e = 0; e < E_NUM; e++) if (e != i1 && p[e] > p[i2]) i2 = e;

        float denom = p[i1] + p[i2];
        float w1 = p[i1] / denom, w2 = p[i2] / denom;
        int r1 = atomicAdd(&g_cnt[i1], 1);
        int r2 = atomicAdd(&g_cnt[i2], 1);
        g_tok_exp[2 * t]     = i1; g_tok_wt[2 * t]     = w1; g_tok_rank[2 * t]     = r1;
        g_tok_exp[2 * t + 1] = i2; g_tok_wt[2 * t + 1] = w2; g_tok_rank[2 * t + 1] = r2;
        if (write_logits) {
#pragma unroll
            for (int e = 0; e < E_NUM; e++)
                logits_out[(size_t)t * E_NUM + e] = l[e];
        }
    }
}

// ---------------- grouped GEMM1: hidden = silu(x@gate) * (x@up) ----------------
// grid.x: row tiles over slots (per-expert), grid.y: I/BN column tiles
__global__ __launch_bounds__(256, 2)
void gemm1_kernel(const float* __restrict__ x,
                  const float* __restrict__ gate_w,
                  const float* __restrict__ up_w) {
    __shared__ int s_e, s_row0, s_end;
    if (threadIdx.x == 0) {
        int b = blockIdx.x, acc = 0, fe = -1, frow0 = 0, fend = 0;
        for (int e = 0; e < E_NUM; e++) {
            int cnt = g_off[e + 1] - g_off[e];
            int nt = (cnt + BM - 1) >> 6;
            if (fe < 0 && b < acc + nt) {
                fe = e; frow0 = g_off[e] + (b - acc) * BM; fend = g_off[e] + cnt;
            }
            acc += nt;
        }
        s_e = fe; s_row0 = frow0; s_end = fend;
    }
    __syncthreads();
    int e = s_e;
    if (e < 0) return;
    int row0 = s_row0, rend = s_end;
    int n0 = blockIdx.y * BN;
    int tid = threadIdx.x, warp = tid >> 5, lane = tid & 31;

    __shared__ int s_tok[BM];
    __shared__ __align__(16) float As[BK][BM];
    __shared__ __align__(16) float Bg[BK][BN];
    __shared__ __align__(16) float Bu[BK][BN];

    if (tid < BM) {
        int r = row0 + tid;
        s_tok[tid] = g_perm[(r < rend) ? r : row0];
    }
    __syncthreads();

    // load lane assignments
    int la_m = tid >> 2, la_k4 = (tid & 3) * 4;           // A: 1 float4 per thread
    int lb_r = tid >> 5, lb_c = lane * 4;                 // B: 2 float4 per thread per matrix

    const float* ax  = x + (size_t)s_tok[la_m] * H_DIM + la_k4;
    const float* bg0 = gate_w + (size_t)e * H_DIM * I_DIM + (size_t)lb_r * I_DIM + n0 + lb_c;
    const float* bu0 = up_w   + (size_t)e * H_DIM * I_DIM + (size_t)lb_r * I_DIM + n0 + lb_c;

    unsigned long long ag[8][2], au[8][2];
#pragma unroll
    for (int i = 0; i < 8; i++) { ag[i][0] = 0ull; ag[i][1] = 0ull; au[i][0] = 0ull; au[i][1] = 0ull; }

    // prefetch tile 0
    float4 ra  = *(const float4*)(ax);
    float4 rg0 = *(const float4*)(bg0);
    float4 rg1 = *(const float4*)(bg0 + 8 * I_DIM);
    float4 ru0 = *(const float4*)(bu0);
    float4 ru1 = *(const float4*)(bu0 + 8 * I_DIM);

    for (int k0 = 0; k0 < H_DIM; k0 += BK) {
        As[la_k4 + 0][la_m] = ra.x; As[la_k4 + 1][la_m] = ra.y;
        As[la_k4 + 2][la_m] = ra.z; As[la_k4 + 3][la_m] = ra.w;
        *(float4*)&Bg[lb_r][lb_c]     = rg0;
        *(float4*)&Bg[lb_r + 8][lb_c] = rg1;
        *(float4*)&Bu[lb_r][lb_c]     = ru0;
        *(float4*)&Bu[lb_r + 8][lb_c] = ru1;
        __syncthreads();

        if (k0 + BK < H_DIM) {
            ra  = *(const float4*)(ax  + k0 + BK);
            rg0 = *(const float4*)(bg0 + (size_t)(k0 + BK) * I_DIM);
            rg1 = *(const float4*)(bg0 + (size_t)(k0 + BK + 8) * I_DIM);
            ru0 = *(const float4*)(bu0 + (size_t)(k0 + BK) * I_DIM);
            ru1 = *(const float4*)(bu0 + (size_t)(k0 + BK + 8) * I_DIM);
        }

#pragma unroll
        for (int k = 0; k < BK; k++) {
            float4 a0 = *(const float4*)(&As[k][warp * 8]);
            float4 a1 = *(const float4*)(&As[k][warp * 8 + 4]);
            ulonglong2 bgv = *(const ulonglong2*)(&Bg[k][lane * 4]);
            ulonglong2 buv = *(const ulonglong2*)(&Bu[k][lane * 4]);
            float av[8] = {a0.x, a0.y, a0.z, a0.w, a1.x, a1.y, a1.z, a1.w};
#pragma unroll
            for (int i = 0; i < 8; i++) {
                unsigned long long ad;
                PACK2(ad, av[i]);
                FMA2(ag[i][0], ad, bgv.x);
                FMA2(ag[i][1], ad, bgv.y);
                FMA2(au[i][0], ad, buv.x);
                FMA2(au[i][1], ad, buv.y);
            }
        }
        __syncthreads();
    }

    int valid_m = rend - row0; if (valid_m > BM) valid_m = BM;
#pragma unroll
    for (int i = 0; i < 8; i++) {
        int m = warp * 8 + i;
        if (m < valid_m) {
            float g0, g1, g2, g3, u0, u1, u2, u3;
            UNPACK2(g0, g1, ag[i][0]); UNPACK2(g2, g3, ag[i][1]);
            UNPACK2(u0, u1, au[i][0]); UNPACK2(u2, u3, au[i][1]);
            float4 o;
            o.x = u0 * (g0 / (1.f + __expf(-g0)));
            o.y = u1 * (g1 / (1.f + __expf(-g1)));
            o.z = u2 * (g2 / (1.f + __expf(-g2)));
            o.w = u3 * (g3 / (1.f + __expf(-g3)));
            *(float4*)(g_hidden + (size_t)(row0 + m) * I_DIM + n0 + lane * 4) = o;
        }
    }
}

// ---------------- grouped GEMM2: out[tok] += w * (hidden @ out_w[e]) ----------------
__global__ __launch_bounds__(256, 2)
void gemm2_kernel(const float* __restrict__ out_w,
                  float* __restrict__ out) {
    __shared__ int s_e, s_row0, s_end;
    if (threadIdx.x == 0) {
        int b = blockIdx.x, acc = 0, fe = -1, frow0 = 0, fend = 0;
        for (int e = 0; e < E_NUM; e++) {
            int cnt = g_off[e + 1] - g_off[e];
            int nt = (cnt + BM - 1) >> 6;
            if (fe < 0 && b < acc + nt) {
                fe = e; frow0 = g_off[e] + (b - acc) * BM; fend = g_off[e] + cnt;
            }
            acc += nt;
        }
        s_e = fe; s_row0 = frow0; s_end = fend;
    }
    __syncthreads();
    int e = s_e;
    if (e < 0) return;
    int row0 = s_row0, rend = s_end;
    int n0 = blockIdx.y * BN;
    int tid = threadIdx.x, warp = tid >> 5, lane = tid & 31;

    __shared__ int   s_tok[BM];
    __shared__ float s_wt[BM];
    __shared__ __align__(16) float As[BK][BM];
    __shared__ __align__(16) float Bs[BK][BN];

    if (tid < BM) {
        int r = row0 + tid;
        int rr = (r < rend) ? r : row0;
        s_tok[tid] = g_perm[rr];
        s_wt[tid]  = g_pwt[rr];
    }
    __syncthreads();

    int la_m = tid >> 2, la_k4 = (tid & 3) * 4;
    int lb_r = tid >> 5, lb_c = lane * 4;

    int arow = row0 + la_m; if (arow >= rend) arow = row0;
    const float* ax = g_hidden + (size_t)arow * I_DIM + la_k4;
    const float* b0 = out_w + (size_t)e * I_DIM * H_DIM + (size_t)lb_r * H_DIM + n0 + lb_c;

    unsigned long long ac[8][2];
#pragma unroll
    for (int i = 0; i < 8; i++) { ac[i][0] = 0ull; ac[i][1] = 0ull; }

    float4 ra  = *(const float4*)(ax);
    float4 rb0 = *(const float4*)(b0);
    float4 rb1 = *(const float4*)(b0 + 8 * H_DIM);

    for (int k0 = 0; k0 < I_DIM; k0 += BK) {
        As[la_k4 + 0][la_m] = ra.x; As[la_k4 + 1][la_m] = ra.y;
        As[la_k4 + 2][la_m] = ra.z; As[la_k4 + 3][la_m] = ra.w;
        *(float4*)&Bs[lb_r][lb_c]     = rb0;
        *(float4*)&Bs[lb_r + 8][lb_c] = rb1;
        __syncthreads();

        if (k0 + BK < I_DIM) {
            ra  = *(const float4*)(ax + k0 + BK);
            rb0 = *(const float4*)(b0 + (size_t)(k0 + BK) * H_DIM);
            rb1 = *(const float4*)(b0 + (size_t)(k0 + BK + 8) * H_DIM);
        }

#pragma unroll
        for (int k = 0; k < BK; k++) {
            float4 a0 = *(const float4*)(&As[k][warp * 8]);
            float4 a1 = *(const float4*)(&As[k][warp * 8 + 4]);
            ulonglong2 bv = *(const ulonglong2*)(&Bs[k][lane * 4]);
            float av[8] = {a0.x, a0.y, a0.z, a0.w, a1.x, a1.y, a1.z, a1.w};
#pragma unroll
            for (int i = 0; i < 8; i++) {
                unsigned long long ad;
                PACK2(ad, av[i]);
                FMA2(ac[i][0], ad, bv.x);
                FMA2(ac[i][1], ad, bv.y);
            }
        }
        __syncthreads();
    }

    int valid_m = rend - row0; if (valid_m > BM) valid_m = BM;
#pragma unroll
    for (int i = 0; i < 8; i++) {
        int m = warp * 8 + i;
        if (m < valid_m) {
            float w = s_wt[m];
            float* op = out + (size_t)s_tok[m] * H_DIM + n0 + lane * 4;
            float o0, o1, o2, o3;
            UNPACK2(o0, o1, ac[i][0]); UNPACK2(o2, o3, ac[i][1]);
            atomicAdd(op + 0, o0 * w);
            atomicAdd(op + 1, o1 * w);
            atomicAdd(op + 2, o2 * w);
            atomicAdd(op + 3, o3 * w);
        }
    }
}

// ---------------- launcher ----------------
extern "C" void kernel_launch(void* const* d_in, const int* in_sizes, int n_in,
                              void* d_out, int out_size) {
    const float* x  = (const float*)d_in[0];   // hidden_states [B,S,H]
    const float* rw = (const float*)d_in[1];   // router_w [H,E]
    const float* gw = (const float*)d_in[2];   // gate_w [E,H,I]
    const float* uw = (const float*)d_in[3];   // up_w   [E,H,I]
    const float* ow = (const float*)d_in[4];   // out_w  [E,I,H]
    float* out = (float*)d_out;

    int write_logits = (out_size >= T_TOK * H_DIM + T_TOK * E_NUM) ? 1 : 0;
    float* logits = out + (size_t)T_TOK * H_DIM;

    cudaMemsetAsync(out, 0, (size_t)T_TOK * H_DIM * sizeof(float), 0);
    zero_cnt_kernel<<<1, 32>>>();
    router_kernel<<<T_TOK, 256>>>(x, rw, logits, write_logits);
    scan_off_kernel<<<1, 32>>>();
    build_perm_kernel<<<(NSLOT + 255) / 256, 256>>>();
    gemm1_kernel<<<dim3(MAX_ROW_TILES, I_DIM / BN), 256>>>(x, gw, uw);
    gemm2_kernel<<<dim3(MAX_ROW_TILES, H_DIM / BN), 256>>>(ow, out);
}